// round 1
// baseline (speedup 1.0000x reference)
#include <cuda_runtime.h>

// QuantumLearnablePositionalEncoding: batched 11-qubit PQC simulation.
//
// Key identities used:
//  * Layer structure = [11 single-qubit gates U=Rz*Ry*Rx] then CNOT(q->q+1) cascade.
//  * The full CNOT cascade is one linear index permutation:
//        new[x] = old[(x ^ (x<<1)) & 2047]          ("graymap")
//  * Layer 1 on |0> yields a tensor-product state:
//        amp[y] = prod_q ( bit_q(y) ? u10_q : u00_q )
//    so layer 1 + its cascade are computed closed-form (no smem passes).
//  * Final cascade is fused into the coalesced output write of Re(state).

#define NQ       11
#define NL       2
#define SDIM     2048              // 2^NQ
#define NTHREADS 256
#define AMPS_PER_T (SDIM / NTHREADS)   // 8

__device__ __forceinline__ int graymap(int x) {
    return (x ^ (x << 1)) & (SDIM - 1);
}

__global__ __launch_bounds__(NTHREADS)
void pqc_kernel(const float* __restrict__ theta,
                const int*   __restrict__ positions,
                float*       __restrict__ out)
{
    __shared__ float sre[SDIM];
    __shared__ float sim[SDIM];
    __shared__ float Ug[NL * NQ][8];   // u00r,u00i,u01r,u01i,u10r,u10i,u11r,u11i

    const int b = blockIdx.x;
    const int t = threadIdx.x;
    const int p = positions[b];
    const float* th = theta + (long long)p * (NL * 3 * NQ);

    // ---- Gate matrices: U = Rz(g)*Ry(b)*Rx(a), all half-angles ----
    if (t < NL * NQ) {
        const int l = t / NQ, q = t - l * NQ;
        const float a  = 0.5f * th[l * 3 * NQ + q * 3 + 0];
        const float bb = 0.5f * th[l * 3 * NQ + q * 3 + 1];
        const float g  = 0.5f * th[l * 3 * NQ + q * 3 + 2];
        float sa, ca, sb, cb, sg, cg;
        sincosf(a,  &sa, &ca);
        sincosf(bb, &sb, &cb);
        sincosf(g,  &sg, &cg);
        const float cbca = cb * ca, sbsa = sb * sa;
        const float sbca = sb * ca, cbsa = cb * sa;
        Ug[t][0] =  cg * cbca + sg * sbsa;   // u00.re
        Ug[t][1] =  cg * sbsa - sg * cbca;   // u00.im
        Ug[t][2] = -cg * sbca - sg * cbsa;   // u01.re
        Ug[t][3] = -cg * cbsa + sg * sbca;   // u01.im
        Ug[t][4] =  cg * sbca + sg * cbsa;   // u10.re
        Ug[t][5] =  sg * sbca - cg * cbsa;   // u10.im
        Ug[t][6] =  cg * cbca + sg * sbsa;   // u11.re
        Ug[t][7] =  sg * cbca - cg * sbsa;   // u11.im
    }
    __syncthreads();

    // ---- Layer 1 (gates + cascade), closed-form init of smem state ----
    // state_for_layer2[x] = prod_q factor_q( bit_q(graymap(x)) )
    {
        // low 8 bits of graymap(x) depend only on t (= low 8 bits of x)
        const int ylow = (t ^ (t << 1)) & 255;
        float pr = 1.f, pi = 0.f;
        #pragma unroll
        for (int q = 0; q < 8; ++q) {
            const float* u = Ug[q];
            const int bit = (ylow >> q) & 1;
            const float fr = bit ? u[4] : u[0];
            const float fi = bit ? u[5] : u[1];
            const float nr = pr * fr - pi * fi;
            const float ni = pr * fi + pi * fr;
            pr = nr; pi = ni;
        }
        #pragma unroll
        for (int k = 0; k < AMPS_PER_T; ++k) {
            const int x = t + (k << 8);
            const int y = graymap(x);
            float rr = pr, ri = pi;
            #pragma unroll
            for (int q = 8; q < NQ; ++q) {
                const float* u = Ug[q];
                const int bit = (y >> q) & 1;
                const float fr = bit ? u[4] : u[0];
                const float fi = bit ? u[5] : u[1];
                const float nr = rr * fr - ri * fi;
                const float ni = rr * fi + ri * fr;
                rr = nr; ri = ni;
            }
            sre[x] = rr; sim[x] = ri;
        }
    }
    __syncthreads();

    // ---- Layer 2: 11 single-qubit gate passes over shared memory ----
    #pragma unroll
    for (int q = 0; q < NQ; ++q) {
        const float* u = Ug[NQ + q];
        const float u00r = u[0], u00i = u[1], u01r = u[2], u01i = u[3];
        const float u10r = u[4], u10i = u[5], u11r = u[6], u11i = u[7];
        const int m = (1 << q) - 1;
        #pragma unroll
        for (int k = 0; k < SDIM / 2 / NTHREADS; ++k) {
            const int pp = t + k * NTHREADS;
            const int i0 = ((pp & ~m) << 1) | (pp & m);
            const int i1 = i0 | (1 << q);
            const float a0r = sre[i0], a0i = sim[i0];
            const float a1r = sre[i1], a1i = sim[i1];
            sre[i0] = u00r*a0r - u00i*a0i + u01r*a1r - u01i*a1i;
            sim[i0] = u00r*a0i + u00i*a0r + u01r*a1i + u01i*a1r;
            sre[i1] = u10r*a0r - u10i*a0i + u11r*a1r - u11i*a1i;
            sim[i1] = u10r*a0i + u10i*a0r + u11r*a1i + u11i*a1r;
        }
        __syncthreads();
    }

    // ---- Final CNOT cascade fused with the output write (real part) ----
    float* ob = out + (long long)b * SDIM;
    #pragma unroll
    for (int k = 0; k < AMPS_PER_T; ++k) {
        const int x = t + k * NTHREADS;
        ob[x] = sre[graymap(x)];
    }
}

extern "C" void kernel_launch(void* const* d_in, const int* in_sizes, int n_in,
                              void* d_out, int out_size)
{
    const float* theta     = (const float*)d_in[0];
    const int*   positions = (const int*)d_in[1];
    float*       out       = (float*)d_out;

    const int batch = in_sizes[1];            // 4096 positions
    pqc_kernel<<<batch, NTHREADS>>>(theta, positions, out);
}

// round 2
// speedup vs baseline: 1.6741x; 1.6741x over previous
#include <cuda_runtime.h>

// Batched 11-qubit PQC simulation, register-resident statevector.
//
//  * CNOT(q->q+1) cascade == index permutation new[x] = old[(x ^ (x<<1)) & 2047].
//  * Layer 1 on |0> is a tensor product -> closed-form init into registers.
//  * Layer 2: 11 commuting single-qubit gates applied where each bit lives:
//      qubits 8-10 : local (register) butterflies
//      qubits 0-4  : warp-shuffle butterflies
//      qubits 5-7  : one smem bit-swap (5-7 <-> 8-10), then register butterflies
//  * Final cascade fused into a re-only smem bounce + coalesced store.

#define NQ       11
#define NL       2
#define SDIM     2048
#define NTHREADS 256

__device__ __forceinline__ int graymap(int x) {
    return (x ^ (x << 1)) & (SDIM - 1);
}

__global__ __launch_bounds__(NTHREADS)
void pqc_kernel(const float* __restrict__ theta,
                const int*   __restrict__ positions,
                float*       __restrict__ out)
{
    __shared__ float sre[SDIM];
    __shared__ float sim[SDIM];
    __shared__ float Ug[NL * NQ][8];   // u00r,u00i,u01r,u01i,u10r,u10i,u11r,u11i

    const int b    = blockIdx.x;
    const int t    = threadIdx.x;
    const int lane = t & 31;
    const int w    = t >> 5;
    const int p    = positions[b];
    const float* th = theta + (long long)p * (NL * 3 * NQ);

    // ---- Gate matrices: U = Rz(g)*Ry(b)*Rx(a), half-angles ----
    if (t < NL * NQ) {
        const int l = t / NQ, q = t - l * NQ;
        const float a  = 0.5f * th[l * 3 * NQ + q * 3 + 0];
        const float bb = 0.5f * th[l * 3 * NQ + q * 3 + 1];
        const float g  = 0.5f * th[l * 3 * NQ + q * 3 + 2];
        float sa, ca, sb, cb, sg, cg;
        sincosf(a,  &sa, &ca);
        sincosf(bb, &sb, &cb);
        sincosf(g,  &sg, &cg);
        const float cbca = cb * ca, sbsa = sb * sa;
        const float sbca = sb * ca, cbsa = cb * sa;
        Ug[t][0] =  cg * cbca + sg * sbsa;
        Ug[t][1] =  cg * sbsa - sg * cbca;
        Ug[t][2] = -cg * sbca - sg * cbsa;
        Ug[t][3] = -cg * cbsa + sg * sbca;
        Ug[t][4] =  cg * sbca + sg * cbsa;
        Ug[t][5] =  sg * sbca - cg * cbsa;
        Ug[t][6] =  cg * cbca + sg * sbsa;
        Ug[t][7] =  sg * cbca - cg * sbsa;
    }
    __syncthreads();

    float ar[8], ai[8];

    // ---- Layer 1 (gates + cascade) closed-form into registers ----
    // state[x] = prod_q factor_q( bit_q(graymap(x)) ),  x = (k<<8) | t
    {
        const int ylow = (t ^ (t << 1)) & 255;   // low 8 bits of graymap(x)
        float pr = 1.f, pi = 0.f;
        #pragma unroll
        for (int q = 0; q < 8; ++q) {
            const float* u = Ug[q];
            const int bit = (ylow >> q) & 1;
            const float fr = bit ? u[4] : u[0];
            const float fi = bit ? u[5] : u[1];
            const float nr = pr * fr - pi * fi;
            const float ni = pr * fi + pi * fr;
            pr = nr; pi = ni;
        }
        #pragma unroll
        for (int k = 0; k < 8; ++k) {
            const int y = graymap((k << 8) | t);
            float rr = pr, ri = pi;
            #pragma unroll
            for (int q = 8; q < NQ; ++q) {
                const float* u = Ug[q];
                const int bit = (y >> q) & 1;
                const float fr = bit ? u[4] : u[0];
                const float fi = bit ? u[5] : u[1];
                const float nr = rr * fr - ri * fi;
                const float ni = rr * fi + ri * fr;
                rr = nr; ri = ni;
            }
            ar[k] = rr; ai[k] = ri;
        }
    }

    // ---- Layer 2 ----

    // Local gates: qubits 8,9,10 live in k bits 0,1,2.
    #pragma unroll
    for (int bq = 0; bq < 3; ++bq) {
        const float* u = Ug[NQ + 8 + bq];
        const float u00r = u[0], u00i = u[1], u01r = u[2], u01i = u[3];
        const float u10r = u[4], u10i = u[5], u11r = u[6], u11i = u[7];
        #pragma unroll
        for (int k = 0; k < 8; ++k) {
            if (k & (1 << bq)) continue;
            const int k1 = k | (1 << bq);
            const float a0r = ar[k],  a0i = ai[k];
            const float a1r = ar[k1], a1i = ai[k1];
            ar[k]  = u00r*a0r - u00i*a0i + u01r*a1r - u01i*a1i;
            ai[k]  = u00r*a0i + u00i*a0r + u01r*a1i + u01i*a1r;
            ar[k1] = u10r*a0r - u10i*a0i + u11r*a1r - u11i*a1i;
            ai[k1] = u10r*a0i + u10i*a0r + u11r*a1i + u11i*a1r;
        }
    }

    // Shuffle gates: qubits 0..4 live in lane bits 0..4.
    #pragma unroll
    for (int q = 0; q < 5; ++q) {
        const float* u = Ug[NQ + q];
        const int bit = (lane >> q) & 1;
        const float csr = bit ? u[6] : u[0];
        const float csi = bit ? u[7] : u[1];
        const float cpr = bit ? u[4] : u[2];
        const float cpi = bit ? u[5] : u[3];
        #pragma unroll
        for (int k = 0; k < 8; ++k) {
            const float prr = __shfl_xor_sync(0xffffffffu, ar[k], 1 << q);
            const float pri = __shfl_xor_sync(0xffffffffu, ai[k], 1 << q);
            const float nr = csr*ar[k] - csi*ai[k] + cpr*prr - cpi*pri;
            const float ni = csr*ai[k] + csi*ar[k] + cpr*pri + cpi*prr;
            ar[k] = nr; ai[k] = ni;
        }
    }

    // Bit-swap transpose via smem: bits 5-7 <-> 8-10.
    #pragma unroll
    for (int k = 0; k < 8; ++k) {
        sre[(k << 8) | t] = ar[k];
        sim[(k << 8) | t] = ai[k];
    }
    __syncthreads();
    #pragma unroll
    for (int k = 0; k < 8; ++k) {
        const int y = (w << 8) | (k << 5) | lane;
        ar[k] = sre[y];
        ai[k] = sim[y];
    }
    // Thread now owns y = (w<<8)|(k<<5)|lane : qubits 5,6,7 are k bits 0,1,2.

    // Local gates: qubits 5,6,7.
    #pragma unroll
    for (int bq = 0; bq < 3; ++bq) {
        const float* u = Ug[NQ + 5 + bq];
        const float u00r = u[0], u00i = u[1], u01r = u[2], u01i = u[3];
        const float u10r = u[4], u10i = u[5], u11r = u[6], u11i = u[7];
        #pragma unroll
        for (int k = 0; k < 8; ++k) {
            if (k & (1 << bq)) continue;
            const int k1 = k | (1 << bq);
            const float a0r = ar[k],  a0i = ai[k];
            const float a1r = ar[k1], a1i = ai[k1];
            ar[k]  = u00r*a0r - u00i*a0i + u01r*a1r - u01i*a1i;
            ai[k]  = u00r*a0i + u00i*a0r + u01r*a1i + u01i*a1r;
            ar[k1] = u10r*a0r - u10i*a0i + u11r*a1r - u11i*a1i;
            ai[k1] = u10r*a0i + u10i*a0r + u11r*a1i + u11i*a1r;
        }
    }

    // Final cascade fused into output: re-only smem bounce, coalesced store.
    __syncthreads();                       // all swap reads of sre done
    #pragma unroll
    for (int k = 0; k < 8; ++k)
        sre[(w << 8) | (k << 5) | lane] = ar[k];
    __syncthreads();

    float* ob = out + (long long)b * SDIM;
    #pragma unroll
    for (int k = 0; k < 8; ++k) {
        const int x = t + (k << 8);
        ob[x] = sre[graymap(x)];
    }
}

extern "C" void kernel_launch(void* const* d_in, const int* in_sizes, int n_in,
                              void* d_out, int out_size)
{
    const float* theta     = (const float*)d_in[0];
    const int*   positions = (const int*)d_in[1];
    float*       out       = (float*)d_out;

    const int batch = in_sizes[1];
    pqc_kernel<<<batch, NTHREADS>>>(theta, positions, out);
}